// round 13
// baseline (speedup 1.0000x reference)
#include <cuda_runtime.h>

typedef unsigned long long ull;

// ---- packed f32x2 helpers (only reachable via PTX, per SASS_QUICKREF) ----
__device__ __forceinline__ ull pk2(float lo, float hi) {
    ull r; asm("mov.b64 %0,{%1,%2};" : "=l"(r) : "f"(lo), "f"(hi)); return r;
}
__device__ __forceinline__ void up2(ull a, float& x, float& y) {
    asm("mov.b64 {%0,%1},%2;" : "=f"(x), "=f"(y) : "l"(a));
}
__device__ __forceinline__ ull fma2(ull a, ull b, ull c) {
    ull d; asm("fma.rn.f32x2 %0,%1,%2,%3;" : "=l"(d) : "l"(a), "l"(b), "l"(c)); return d;
}
__device__ __forceinline__ ull add2(ull a, ull b) {
    ull d; asm("add.rn.f32x2 %0,%1,%2;" : "=l"(d) : "l"(a), "l"(b)); return d;
}

// Interval-pruned linear-split formulation (R12 core):
//   - input loads issued BEFORE the build phase (DRAM latency overlaps build)
//   - tmin>0 -> fold w2*(u,v,c) into linear term; tmax<0 -> drop;
//     straddling -> 0.5*w2*(u,v,c) linear + sign*|t''| in the loop
//   - out = dCb + dU*A + dV*B + Sum_pos|t''| - Sum_neg|t''|  (exact)
// R13: 256-thread blocks (half the build instances) and min-blocks 5 to force
// regs <= 51 -> 40 resident warps/SM (up from 36) on a latency-bound kernel.
__global__ void __launch_bounds__(256, 5) simplenn_kernel(
    const float* __restrict__ x,
    const float* __restrict__ gate,
    const float* __restrict__ w1,   // (2,64) row-major
    const float* __restrict__ b1,   // (64,)
    const float* __restrict__ w2,   // (64,1)
    const float* __restrict__ b2,   // (1,)
    float* __restrict__ out,        // (B,5)
    int npairs)
{
    __shared__ ulonglong2 wuv[64];  // (uu, vv) per straddling unit -> one LDS.128
    __shared__ ull wc[64];          // (cc)                          -> one LDS.64
    __shared__ float s_red[2][3];   // per-warp partials of (du, dv, dc)
    __shared__ int s_cnt[4];        // straddler counts by w2 sign, per warp
    __shared__ int s_NPOSa, s_NACT;

    int tid  = threadIdx.x;
    int lane = tid & 31;

    // ---- issue input loads FIRST: 2 rows = 80B, 5x LDG.128, coalesced ----
    // Their ~600-cycle DRAM latency overlaps the entire build phase below.
    int t = blockIdx.x * 256 + tid;
    int tl = t < npairs ? t : npairs - 1;   // clamp so every thread reaches barriers
    float4 f0, f1, f2, f3, f4;
    {
        const float4* xp = (const float4*)(x + (size_t)tl * 20);
        f0 = xp[0]; f1 = xp[1]; f2 = xp[2]; f3 = xp[3]; f4 = xp[4];
    }

    // argmax(gate_logits) — runtime-constant, uniform across all threads
    float g0 = gate[0], g1 = gate[1], g2 = gate[2], g3 = gate[3];
    int idx = 0; float best = g0;
    if (g1 > best) { best = g1; idx = 1; }
    if (g2 > best) { best = g2; idx = 2; }
    if (g3 > best) { best = g3; idx = 3; }

    // Domain box of the selected transform over x in (0.01, 1.0), widened by
    // 1e-4 to absorb fast-intrinsic ulp error and corner-eval rounding.
    float blo, bhi;
    if      (idx == 0) { blo = 0.01f;         bhi = 1.0f;        }
    else if (idx == 1) { blo = -4.60517019f;  bhi = 0.0f;        }
    else if (idx == 2) { blo = 1.01005017f;   bhi = 2.71828183f; }
    else               { blo = 0.00999983f;   bhi = 0.84147098f; }
    blo -= 1e-4f; bhi += 1e-4f;

    // ---- build phase: classify units, fold linear parts, compact straddlers ----
    unsigned mP = 0, mN = 0;
    bool isS = false, wpos = true;
    float su = 0.f, sv = 0.f, sc = 0.f;
    if (tid < 64) {   // warps 0 and 1 fully active here
        float u = w1[tid];
        float v = w1[64 + tid];
        float c = b1[tid];
        float w = w2[tid];

        // corner extremes of t = u*A + v*B + c over the box (affine -> corners)
        float t00 = fmaf(u, blo, fmaf(v, blo, c));
        float t01 = fmaf(u, blo, fmaf(v, bhi, c));
        float t10 = fmaf(u, bhi, fmaf(v, blo, c));
        float t11 = fmaf(u, bhi, fmaf(v, bhi, c));
        float tmin = fminf(fminf(t00, t01), fminf(t10, t11));
        float tmax = fmaxf(fmaxf(t00, t01), fmaxf(t10, t11));
        bool isP = (tmin > 0.0f);    // always-on: exactly linear
        bool isN = (tmax < 0.0f);    // always-off: drop
        isS  = !(isP || isN);        // straddling: keep hinge
        wpos = (w >= 0.0f);

        float aw = 0.5f * fabsf(w);
        su = aw * u; sv = aw * v; sc = aw * c;

        // linear fold coefficient: P -> w, S -> 0.5*w, N -> 0
        float coef = isP ? w : (isS ? 0.5f * w : 0.0f);
        float du = coef * u, dv = coef * v, dc = coef * c;

        mP = __ballot_sync(0xffffffffu, isS && wpos);
        mN = __ballot_sync(0xffffffffu, isS && !wpos);

        #pragma unroll
        for (int o = 16; o > 0; o >>= 1) {
            du += __shfl_xor_sync(0xffffffffu, du, o);
            dv += __shfl_xor_sync(0xffffffffu, dv, o);
            dc += __shfl_xor_sync(0xffffffffu, dc, o);
        }
        if (lane == 0) {
            int w_ = tid >> 5;
            s_red[w_][0] = du; s_red[w_][1] = dv; s_red[w_][2] = dc;
            s_cnt[w_]     = __popc(mP);
            s_cnt[2 + w_] = __popc(mN);
        }
    }
    __syncthreads();

    if (tid < 64 && isS) {
        int nP0 = s_cnt[0], nP1 = s_cnt[1], nN0 = s_cnt[2];
        int NPOSa = nP0 + nP1;
        unsigned below = (1u << lane) - 1u;
        int slot;
        if (wpos) slot = __popc(mP & below) + (tid >= 32 ? nP0 : 0);
        else      slot = NPOSa + __popc(mN & below) + (tid >= 32 ? nN0 : 0);
        wuv[slot] = make_ulonglong2(pk2(su, su), pk2(sv, sv));
        wc[slot]  = pk2(sc, sc);
    }
    if (tid == 0) {
        int NPOSa = s_cnt[0] + s_cnt[1];
        s_NPOSa = NPOSa;
        s_NACT  = NPOSa + s_cnt[2] + s_cnt[3];
    }
    __syncthreads();

    if (t >= npairs) return;

    int NPOSa = s_NPOSa;
    int NACT  = s_NACT;
    float dU  = s_red[0][0] + s_red[1][0];
    float dV  = s_red[0][1] + s_red[1][1];
    float dCb = s_red[0][2] + s_red[1][2] + b2[0];

    // Inputs already in registers; spread to scalar array
    float v20[20];
    v20[0]=f0.x; v20[1]=f0.y; v20[2]=f0.z; v20[3]=f0.w;
    v20[4]=f1.x; v20[5]=f1.y; v20[6]=f1.z; v20[7]=f1.w;
    v20[8]=f2.x; v20[9]=f2.y; v20[10]=f2.z; v20[11]=f2.w;
    v20[12]=f3.x; v20[13]=f3.y; v20[14]=f3.z; v20[15]=f3.w;
    v20[16]=f4.x; v20[17]=f4.y; v20[18]=f4.z; v20[19]=f4.w;

    // Apply selected transform (uniform branch; MUFU-based intrinsics)
    if (idx == 1) {
        #pragma unroll
        for (int i = 0; i < 20; i++) v20[i] = __logf(v20[i]);
    } else if (idx == 2) {
        #pragma unroll
        for (int i = 0; i < 20; i++) v20[i] = __expf(v20[i]);
    } else if (idx == 3) {
        #pragma unroll
        for (int i = 0; i < 20; i++) v20[i] = __sinf(v20[i]);
    }

    // 5 chains; acc initialized with the full linear term (epilogue-free)
    ull dU2  = pk2(dU, dU);
    ull dV2  = pk2(dV, dV);
    ull dCb2 = pk2(dCb, dCb);

    ull A[5], Bp[5], acc[5];
    #pragma unroll
    for (int i = 0; i < 5; i++) {
        A[i]   = pk2(v20[i],     v20[10 + i]);
        Bp[i]  = pk2(v20[5 + i], v20[15 + i]);
        acc[i] = fma2(A[i], dU2, fma2(Bp[i], dV2, dCb2));   // lin folded into init
    }

    // Straddling positive-w2 units: acc += |t''|   (AND with immediate mask)
    #pragma unroll 4
    for (int j = 0; j < NPOSa; j++) {
        ulonglong2 p = wuv[j];          // one LDS.128: (uu, vv)
        ull cc = wc[j];                 // one LDS.64
        #pragma unroll
        for (int i = 0; i < 5; i++) {
            ull t2 = fma2(A[i], p.x, fma2(Bp[i], p.y, cc));
            acc[i] = add2(acc[i], t2 & 0x7FFFFFFF7FFFFFFFULL);
        }
    }
    // Straddling negative-w2 units: acc += -|t''|  (OR sign bit)
    #pragma unroll 4
    for (int j = NPOSa; j < NACT; j++) {
        ulonglong2 p = wuv[j];
        ull cc = wc[j];
        #pragma unroll
        for (int i = 0; i < 5; i++) {
            ull t2 = fma2(A[i], p.x, fma2(Bp[i], p.y, cc));
            acc[i] = add2(acc[i], t2 | 0x8000000080000000ULL);
        }
    }

    // Pure unpack + store: 10 contiguous floats
    float r0[5], r1[5];
    #pragma unroll
    for (int i = 0; i < 5; i++) up2(acc[i], r0[i], r1[i]);

    float2* op = (float2*)(out + (size_t)t * 10);
    op[0] = make_float2(r0[0], r0[1]);
    op[1] = make_float2(r0[2], r0[3]);
    op[2] = make_float2(r0[4], r1[0]);
    op[3] = make_float2(r1[1], r1[2]);
    op[4] = make_float2(r1[3], r1[4]);
}

extern "C" void kernel_launch(void* const* d_in, const int* in_sizes, int n_in,
                              void* d_out, int out_size) {
    const float* x    = (const float*)d_in[0];
    const float* gate = (const float*)d_in[1];
    const float* w1   = (const float*)d_in[2];
    const float* b1   = (const float*)d_in[3];
    const float* w2   = (const float*)d_in[4];
    const float* b2   = (const float*)d_in[5];
    float* out = (float*)d_out;

    int nrows  = in_sizes[0] / 10;   // BATCH
    int npairs = nrows / 2;          // 2 rows per thread (BATCH is even)
    int blocks = (npairs + 255) / 256;

    simplenn_kernel<<<blocks, 256>>>(x, gate, w1, b1, w2, b2, out, npairs);
}

// round 14
// speedup vs baseline: 1.1936x; 1.1936x over previous
#include <cuda_runtime.h>

typedef unsigned long long ull;

// ---- packed f32x2 helpers (only reachable via PTX, per SASS_QUICKREF) ----
__device__ __forceinline__ ull pk2(float lo, float hi) {
    ull r; asm("mov.b64 %0,{%1,%2};" : "=l"(r) : "f"(lo), "f"(hi)); return r;
}
__device__ __forceinline__ void up2(ull a, float& x, float& y) {
    asm("mov.b64 {%0,%1},%2;" : "=f"(x), "=f"(y) : "l"(a));
}
__device__ __forceinline__ ull fma2(ull a, ull b, ull c) {
    ull d; asm("fma.rn.f32x2 %0,%1,%2,%3;" : "=l"(d) : "l"(a), "l"(b), "l"(c)); return d;
}

// Interval-pruned linear-split formulation (R12 core, R12 launch shape):
//   - input loads issued BEFORE the build phase (DRAM latency overlaps build)
//   - tmin>0 -> fold w2*(u,v,c) into linear term; tmax<0 -> drop;
//     straddling -> 0.5*w2*(u,v,c) linear + sign*|t''| in the loop
//   - out = dCb + dU*A + dV*B + Sum_pos|t''| - Sum_neg|t''|  (exact)
// R14: scalar accumulators with modifier-folded abs-accumulate:
//   acc += fabsf(h)  ->  single FADD R,R,|R|   (no LOP3, no add2, no unpack)
// Per unit-chain: fma2, fma2, FADD, FADD = 4 issue slots (was 5).
__global__ void __launch_bounds__(128) simplenn_kernel(
    const float* __restrict__ x,
    const float* __restrict__ gate,
    const float* __restrict__ w1,   // (2,64) row-major
    const float* __restrict__ b1,   // (64,)
    const float* __restrict__ w2,   // (64,1)
    const float* __restrict__ b2,   // (1,)
    float* __restrict__ out,        // (B,5)
    int npairs)
{
    __shared__ ulonglong2 wuv[64];  // (uu, vv) per straddling unit -> one LDS.128
    __shared__ ull wc[64];          // (cc)                          -> one LDS.64
    __shared__ float s_red[2][3];   // per-warp partials of (du, dv, dc)
    __shared__ int s_cnt[4];        // straddler counts by w2 sign, per warp
    __shared__ int s_NPOSa, s_NACT;

    int tid  = threadIdx.x;
    int lane = tid & 31;

    // ---- issue input loads FIRST: 2 rows = 80B, 5x LDG.128, coalesced ----
    // Their ~600-cycle DRAM latency overlaps the entire build phase below.
    int t = blockIdx.x * 128 + tid;
    int tl = t < npairs ? t : npairs - 1;   // clamp so every thread reaches barriers
    float4 f0, f1, f2, f3, f4;
    {
        const float4* xp = (const float4*)(x + (size_t)tl * 20);
        f0 = xp[0]; f1 = xp[1]; f2 = xp[2]; f3 = xp[3]; f4 = xp[4];
    }

    // argmax(gate_logits) — runtime-constant, uniform across all threads
    float g0 = gate[0], g1 = gate[1], g2 = gate[2], g3 = gate[3];
    int idx = 0; float best = g0;
    if (g1 > best) { best = g1; idx = 1; }
    if (g2 > best) { best = g2; idx = 2; }
    if (g3 > best) { best = g3; idx = 3; }

    // Domain box of the selected transform over x in (0.01, 1.0), widened by
    // 1e-4 to absorb fast-intrinsic ulp error and corner-eval rounding.
    float blo, bhi;
    if      (idx == 0) { blo = 0.01f;         bhi = 1.0f;        }
    else if (idx == 1) { blo = -4.60517019f;  bhi = 0.0f;        }
    else if (idx == 2) { blo = 1.01005017f;   bhi = 2.71828183f; }
    else               { blo = 0.00999983f;   bhi = 0.84147098f; }
    blo -= 1e-4f; bhi += 1e-4f;

    // ---- build phase: classify units, fold linear parts, compact straddlers ----
    unsigned mP = 0, mN = 0;
    bool isS = false, wpos = true;
    float su = 0.f, sv = 0.f, sc = 0.f;
    if (tid < 64) {   // warps 0 and 1 fully active here
        float u = w1[tid];
        float v = w1[64 + tid];
        float c = b1[tid];
        float w = w2[tid];

        // corner extremes of t = u*A + v*B + c over the box (affine -> corners)
        float t00 = fmaf(u, blo, fmaf(v, blo, c));
        float t01 = fmaf(u, blo, fmaf(v, bhi, c));
        float t10 = fmaf(u, bhi, fmaf(v, blo, c));
        float t11 = fmaf(u, bhi, fmaf(v, bhi, c));
        float tmin = fminf(fminf(t00, t01), fminf(t10, t11));
        float tmax = fmaxf(fmaxf(t00, t01), fmaxf(t10, t11));
        bool isP = (tmin > 0.0f);    // always-on: exactly linear
        bool isN = (tmax < 0.0f);    // always-off: drop
        isS  = !(isP || isN);        // straddling: keep hinge
        wpos = (w >= 0.0f);

        float aw = 0.5f * fabsf(w);
        su = aw * u; sv = aw * v; sc = aw * c;

        // linear fold coefficient: P -> w, S -> 0.5*w, N -> 0
        float coef = isP ? w : (isS ? 0.5f * w : 0.0f);
        float du = coef * u, dv = coef * v, dc = coef * c;

        mP = __ballot_sync(0xffffffffu, isS && wpos);
        mN = __ballot_sync(0xffffffffu, isS && !wpos);

        #pragma unroll
        for (int o = 16; o > 0; o >>= 1) {
            du += __shfl_xor_sync(0xffffffffu, du, o);
            dv += __shfl_xor_sync(0xffffffffu, dv, o);
            dc += __shfl_xor_sync(0xffffffffu, dc, o);
        }
        if (lane == 0) {
            int w_ = tid >> 5;
            s_red[w_][0] = du; s_red[w_][1] = dv; s_red[w_][2] = dc;
            s_cnt[w_]     = __popc(mP);
            s_cnt[2 + w_] = __popc(mN);
        }
    }
    __syncthreads();

    if (tid < 64 && isS) {
        int nP0 = s_cnt[0], nP1 = s_cnt[1], nN0 = s_cnt[2];
        int NPOSa = nP0 + nP1;
        unsigned below = (1u << lane) - 1u;
        int slot;
        if (wpos) slot = __popc(mP & below) + (tid >= 32 ? nP0 : 0);
        else      slot = NPOSa + __popc(mN & below) + (tid >= 32 ? nN0 : 0);
        wuv[slot] = make_ulonglong2(pk2(su, su), pk2(sv, sv));
        wc[slot]  = pk2(sc, sc);
    }
    if (tid == 0) {
        int NPOSa = s_cnt[0] + s_cnt[1];
        s_NPOSa = NPOSa;
        s_NACT  = NPOSa + s_cnt[2] + s_cnt[3];
    }
    __syncthreads();

    if (t >= npairs) return;

    int NPOSa = s_NPOSa;
    int NACT  = s_NACT;
    float dU  = s_red[0][0] + s_red[1][0];
    float dV  = s_red[0][1] + s_red[1][1];
    float dCb = s_red[0][2] + s_red[1][2] + b2[0];

    // Inputs already in registers; spread to scalar array
    float v20[20];
    v20[0]=f0.x; v20[1]=f0.y; v20[2]=f0.z; v20[3]=f0.w;
    v20[4]=f1.x; v20[5]=f1.y; v20[6]=f1.z; v20[7]=f1.w;
    v20[8]=f2.x; v20[9]=f2.y; v20[10]=f2.z; v20[11]=f2.w;
    v20[12]=f3.x; v20[13]=f3.y; v20[14]=f3.z; v20[15]=f3.w;
    v20[16]=f4.x; v20[17]=f4.y; v20[18]=f4.z; v20[19]=f4.w;

    // Apply selected transform (uniform branch; MUFU-based intrinsics)
    if (idx == 1) {
        #pragma unroll
        for (int i = 0; i < 20; i++) v20[i] = __logf(v20[i]);
    } else if (idx == 2) {
        #pragma unroll
        for (int i = 0; i < 20; i++) v20[i] = __expf(v20[i]);
    } else if (idx == 3) {
        #pragma unroll
        for (int i = 0; i < 20; i++) v20[i] = __sinf(v20[i]);
    }

    // 5 chains, SCALAR accumulators (aP = row0 elem i, aQ = row1 elem i),
    // initialized with the full linear term (epilogue-free).
    ull dU2  = pk2(dU, dU);
    ull dV2  = pk2(dV, dV);
    ull dCb2 = pk2(dCb, dCb);

    ull A[5], Bp[5];
    float aP[5], aQ[5];
    #pragma unroll
    for (int i = 0; i < 5; i++) {
        A[i]  = pk2(v20[i],     v20[10 + i]);
        Bp[i] = pk2(v20[5 + i], v20[15 + i]);
        ull lin = fma2(A[i], dU2, fma2(Bp[i], dV2, dCb2));
        up2(lin, aP[i], aQ[i]);    // pair-rename, no real movs
    }

    // Straddling positive-w2 units: acc += |t''|  (FADD with |src| modifier)
    #pragma unroll 4
    for (int j = 0; j < NPOSa; j++) {
        ulonglong2 p = wuv[j];          // one LDS.128: (uu, vv)
        ull cc = wc[j];                 // one LDS.64
        #pragma unroll
        for (int i = 0; i < 5; i++) {
            ull t2 = fma2(A[i], p.x, fma2(Bp[i], p.y, cc));
            float h0, h1;
            up2(t2, h0, h1);            // pair-rename
            aP[i] += fabsf(h0);         // FADD R,R,|R|
            aQ[i] += fabsf(h1);
        }
    }
    // Straddling negative-w2 units: acc -= |t''|  (FADD with -|src| modifier)
    #pragma unroll 4
    for (int j = NPOSa; j < NACT; j++) {
        ulonglong2 p = wuv[j];
        ull cc = wc[j];
        #pragma unroll
        for (int i = 0; i < 5; i++) {
            ull t2 = fma2(A[i], p.x, fma2(Bp[i], p.y, cc));
            float h0, h1;
            up2(t2, h0, h1);
            aP[i] -= fabsf(h0);         // FADD R,R,-|R|
            aQ[i] -= fabsf(h1);
        }
    }

    // Direct scalar stores: 10 contiguous floats
    float2* op = (float2*)(out + (size_t)t * 10);
    op[0] = make_float2(aP[0], aP[1]);
    op[1] = make_float2(aP[2], aP[3]);
    op[2] = make_float2(aP[4], aQ[0]);
    op[3] = make_float2(aQ[1], aQ[2]);
    op[4] = make_float2(aQ[3], aQ[4]);
}

extern "C" void kernel_launch(void* const* d_in, const int* in_sizes, int n_in,
                              void* d_out, int out_size) {
    const float* x    = (const float*)d_in[0];
    const float* gate = (const float*)d_in[1];
    const float* w1   = (const float*)d_in[2];
    const float* b1   = (const float*)d_in[3];
    const float* w2   = (const float*)d_in[4];
    const float* b2   = (const float*)d_in[5];
    float* out = (float*)d_out;

    int nrows  = in_sizes[0] / 10;   // BATCH
    int npairs = nrows / 2;          // 2 rows per thread (BATCH is even)
    int blocks = (npairs + 127) / 128;

    simplenn_kernel<<<blocks, 128>>>(x, gate, w1, b1, w2, b2, out, npairs);
}